// round 2
// baseline (speedup 1.0000x reference)
#include <cuda_runtime.h>
#include <cstddef>

typedef unsigned long long u64;

// Scratch (static __device__ — no allocations allowed).
__device__ float g_S[1966080];    // softmaxed weights, all 4 layers
__device__ float g_hA[2097152];   // 512*256*16 (layer1 out, reused by layer3 out)
__device__ float g_hB[1048576];   // 512*128*16 (layer2 out, reused by layer4 out)

// ---------------- packed f32x2 helpers (Blackwell dual-fp32 pipe) ----------
__device__ __forceinline__ void fma2(u64& d, u64 a, u64 b) {
    asm("fma.rn.f32x2 %0, %1, %2, %0;" : "+l"(d) : "l"(a), "l"(b));
}
__device__ __forceinline__ u64 add2(u64 a, u64 b) {
    u64 d; asm("add.rn.f32x2 %0, %1, %2;" : "=l"(d) : "l"(a), "l"(b)); return d;
}
__device__ __forceinline__ u64 pack2(float x) {
    u64 d; asm("mov.b64 %0, {%1, %1};" : "=l"(d) : "f"(x)); return d;
}
__device__ __forceinline__ void unpack2(u64 a, float& lo, float& hi) {
    asm("mov.b64 {%0, %1}, %2;" : "=f"(lo), "=f"(hi) : "l"(a));
}

// ---------------------------------------------------------------------------
// Kernel 1: weight softmax. One block per f-slice (480 blocks, 256 threads).
// Slice (256 m x 16 k) is staged in smem; per-k max/sum via smem tree reduce;
// normalized slice written back coalesced.
// ---------------------------------------------------------------------------
__global__ void __launch_bounds__(256) wsoftmax_kernel(
    const float* __restrict__ W1, const float* __restrict__ W2,
    const float* __restrict__ W3, const float* __restrict__ W4)
{
    __shared__ float Ssm[4096];
    __shared__ float red[256];
    __shared__ float mxk[16];

    const int bx = blockIdx.x;
    const int t  = threadIdx.x;
    const float* W; float* S; int f;
    if (bx < 256)      { W = W1; S = g_S;           f = bx;       }
    else if (bx < 384) { W = W2; S = g_S + 1048576; f = bx - 256; }
    else if (bx < 448) { W = W3; S = g_S + 1572864; f = bx - 384; }
    else               { W = W4; S = g_S + 1835008; f = bx - 448; }

    const float4* Wg = (const float4*)(W + (size_t)f * 4096);
    float4*       Sg = (float4*)(S + (size_t)f * 4096);

    // stage slice, coalesced
    #pragma unroll
    for (int q = 0; q < 4; q++) ((float4*)Ssm)[t + 256 * q] = Wg[t + 256 * q];
    __syncthreads();

    const int k = t & 15;      // class column
    const int g = t >> 4;      // m-group (16 m each)

    // per-k max
    float pm = -1e30f;
    #pragma unroll
    for (int mm = 0; mm < 16; mm++) pm = fmaxf(pm, Ssm[(g * 16 + mm) * 16 + k]);
    red[g * 16 + k] = pm;
    __syncthreads();
    #pragma unroll
    for (int st = 8; st > 0; st >>= 1) {
        if (g < st) red[g * 16 + k] = fmaxf(red[g * 16 + k], red[(g + st) * 16 + k]);
        __syncthreads();
    }
    if (g == 0) mxk[k] = red[k];
    __syncthreads();

    // exp + per-k sum
    const float mx = mxk[k];
    float ps = 0.f;
    #pragma unroll
    for (int mm = 0; mm < 16; mm++) {
        int idx = (g * 16 + mm) * 16 + k;
        float e = __expf(Ssm[idx] - mx);
        Ssm[idx] = e;
        ps += e;
    }
    __syncthreads();           // all mx reads done before red reuse
    red[g * 16 + k] = ps;
    __syncthreads();
    #pragma unroll
    for (int st = 8; st > 0; st >>= 1) {
        if (g < st) red[g * 16 + k] += red[(g + st) * 16 + k];
        __syncthreads();
    }
    const float inv = 1.f / red[k];
    #pragma unroll
    for (int mm = 0; mm < 16; mm++) Ssm[(g * 16 + mm) * 16 + k] *= inv;
    __syncthreads();

    // write back, coalesced
    #pragma unroll
    for (int q = 0; q < 4; q++) Sg[t + 256 * q] = ((float4*)Ssm)[t + 256 * q];
}

// ---------------------------------------------------------------------------
// Kernel 2: one SPN layer, 4-way m-split + packed f32x2 FMA.
// Block = (f_out, n-tile of 32), 128 threads: n_local = tid>>2, s = tid&3.
// Thread handles i in [4s, 4s+4); acc[16] kept as 8 f32x2 regs; reduced
// across the 4 split-threads with shfl.xor; lane s==0 does log + store.
// ---------------------------------------------------------------------------
__global__ void __launch_bounds__(128) layer_kernel(
    const float* __restrict__ hin, const float* __restrict__ Sall,
    float* __restrict__ hout, int F_in, int s_off)
{
    __shared__ float Ssm[4096];

    const int f   = blockIdx.x;
    const int tid = threadIdx.x;
    const int s   = tid & 3;
    const int n   = blockIdx.y * 32 + (tid >> 2);
    const int F_out = F_in >> 1;

    // cooperative stage of S_f (16KB), coalesced
    {
        const float4* Sg = (const float4*)(Sall + (size_t)s_off + (size_t)f * 4096);
        #pragma unroll
        for (int q = 0; q < 8; q++) ((float4*)Ssm)[tid + 128 * q] = Sg[tid + 128 * q];
    }

    // load children (left 16 + right 16 floats)
    const float4* hp = (const float4*)(hin + ((size_t)n * F_in + 2 * f) * 16);
    float4 L0 = hp[0], L1 = hp[1], L2 = hp[2], L3 = hp[3];
    float4 R0 = hp[4], R1 = hp[5], R2 = hp[6], R3 = hp[7];

    float lmax = fmaxf(fmaxf(fmaxf(L0.x, L0.y), fmaxf(L0.z, L0.w)),
                 fmaxf(fmaxf(fmaxf(L1.x, L1.y), fmaxf(L1.z, L1.w)),
                 fmaxf(fmaxf(fmaxf(L2.x, L2.y), fmaxf(L2.z, L2.w)),
                       fmaxf(fmaxf(L3.x, L3.y), fmaxf(L3.z, L3.w)))));
    float rmax = fmaxf(fmaxf(fmaxf(R0.x, R0.y), fmaxf(R0.z, R0.w)),
                 fmaxf(fmaxf(fmaxf(R1.x, R1.y), fmaxf(R1.z, R1.w)),
                 fmaxf(fmaxf(fmaxf(R2.x, R2.y), fmaxf(R2.z, R2.w)),
                       fmaxf(fmaxf(R3.x, R3.y), fmaxf(R3.z, R3.w)))));

    // this thread's 4 'a' values: left quad #s
    float4 La = hp[s];
    const float a0 = __expf(La.x - lmax);
    const float a1 = __expf(La.y - lmax);
    const float a2 = __expf(La.z - lmax);
    const float a3 = __expf(La.w - lmax);

    float b[16];
    b[0]=__expf(R0.x-rmax); b[1]=__expf(R0.y-rmax); b[2]=__expf(R0.z-rmax); b[3]=__expf(R0.w-rmax);
    b[4]=__expf(R1.x-rmax); b[5]=__expf(R1.y-rmax); b[6]=__expf(R1.z-rmax); b[7]=__expf(R1.w-rmax);
    b[8]=__expf(R2.x-rmax); b[9]=__expf(R2.y-rmax); b[10]=__expf(R2.z-rmax); b[11]=__expf(R2.w-rmax);
    b[12]=__expf(R3.x-rmax); b[13]=__expf(R3.y-rmax); b[14]=__expf(R3.z-rmax); b[15]=__expf(R3.w-rmax);

    __syncthreads();   // Ssm ready

    u64 acc[8];
    #pragma unroll
    for (int q = 0; q < 8; q++) acc[q] = 0ull;

    const int ibase = 4 * s;
    #pragma unroll
    for (int i = 0; i < 4; i++) {
        const float ai = (i == 0) ? a0 : (i == 1) ? a1 : (i == 2) ? a2 : a3;
        // row base for m = (ibase+i)*16 + j, each row = 16 floats = 4x 16B
        const ulonglong2* rowb =
            (const ulonglong2*)(Ssm + ((ibase + i) * 16) * 16);
        #pragma unroll
        for (int j = 0; j < 16; j++) {
            const float p = ai * b[j];
            const u64 p2 = pack2(p);
            const ulonglong2 q0 = rowb[j * 4 + 0];
            const ulonglong2 q1 = rowb[j * 4 + 1];
            const ulonglong2 q2 = rowb[j * 4 + 2];
            const ulonglong2 q3 = rowb[j * 4 + 3];
            fma2(acc[0], p2, q0.x); fma2(acc[1], p2, q0.y);
            fma2(acc[2], p2, q1.x); fma2(acc[3], p2, q1.y);
            fma2(acc[4], p2, q2.x); fma2(acc[5], p2, q2.y);
            fma2(acc[6], p2, q3.x); fma2(acc[7], p2, q3.y);
        }
    }

    // reduce across the 4 split-threads (lanes s, s^1, s^2)
    #pragma unroll
    for (int q = 0; q < 8; q++)
        acc[q] = add2(acc[q], __shfl_xor_sync(0xffffffffu, acc[q], 1));
    #pragma unroll
    for (int q = 0; q < 8; q++)
        acc[q] = add2(acc[q], __shfl_xor_sync(0xffffffffu, acc[q], 2));

    if (s == 0) {
        const float base = lmax + rmax;
        float o[16];
        #pragma unroll
        for (int q = 0; q < 8; q++) {
            float lo, hi; unpack2(acc[q], lo, hi);
            o[2 * q]     = __logf(lo) + base;
            o[2 * q + 1] = __logf(hi) + base;
        }
        float4* op = (float4*)(hout + ((size_t)n * F_out + f) * 16);
        #pragma unroll
        for (int q = 0; q < 4; q++) op[q] = ((float4*)o)[q];
    }
}

// ---------------------------------------------------------------------------
// Kernel 3: root. hs[n][c] = sum_f h4[n][f][c] (f=0..31), then
// out[n] = logsumexp_c( hs[n][c] + log_softmax(W_root)[c] ).
// ---------------------------------------------------------------------------
__global__ void root_kernel(const float* __restrict__ h4,
                            const float* __restrict__ Wroot,
                            float* __restrict__ out)
{
    int n = blockIdx.x * blockDim.x + threadIdx.x;
    if (n >= 512) return;

    float s[16];
    #pragma unroll
    for (int k = 0; k < 16; k++) s[k] = 0.f;

    const float4* hp = (const float4*)(h4 + (size_t)n * 512);
    #pragma unroll
    for (int t = 0; t < 128; t++) {
        float4 q = hp[t];
        const int k0 = (t & 3) * 4;
        s[k0 + 0] += q.x; s[k0 + 1] += q.y; s[k0 + 2] += q.z; s[k0 + 3] += q.w;
    }

    float w[16];
    #pragma unroll
    for (int k = 0; k < 16; k++) w[k] = Wroot[k];
    float wm = w[0];
    #pragma unroll
    for (int k = 1; k < 16; k++) wm = fmaxf(wm, w[k]);
    float Z = 0.f;
    #pragma unroll
    for (int k = 0; k < 16; k++) Z += __expf(w[k] - wm);
    const float lz = __logf(Z) + wm;

    float t[16];
    float tm = -1e30f;
    #pragma unroll
    for (int k = 0; k < 16; k++) {
        t[k] = s[k] + w[k] - lz;
        tm = fmaxf(tm, t[k]);
    }
    float ss = 0.f;
    #pragma unroll
    for (int k = 0; k < 16; k++) ss += __expf(t[k] - tm);
    out[n] = __logf(ss) + tm;
}

// ---------------------------------------------------------------------------
extern "C" void kernel_launch(void* const* d_in, const int* in_sizes, int n_in,
                              void* d_out, int out_size)
{
    const float* x  = (const float*)d_in[0];
    const float* W1 = (const float*)d_in[1];
    const float* W2 = (const float*)d_in[2];
    const float* W3 = (const float*)d_in[3];
    const float* W4 = (const float*)d_in[4];
    const float* Wr = (const float*)d_in[5];
    float* out = (float*)d_out;

    float *S, *hA, *hB;
    cudaGetSymbolAddress((void**)&S,  g_S);
    cudaGetSymbolAddress((void**)&hA, g_hA);
    cudaGetSymbolAddress((void**)&hB, g_hB);

    wsoftmax_kernel<<<480, 256>>>(W1, W2, W3, W4);

    layer_kernel<<<dim3(256, 16), 128>>>(x,  S, hA, 512, 0);        // F 512->256
    layer_kernel<<<dim3(128, 16), 128>>>(hA, S, hB, 256, 1048576);  // F 256->128
    layer_kernel<<<dim3(64, 16),  128>>>(hB, S, hA, 128, 1572864);  // F 128->64
    layer_kernel<<<dim3(32, 16),  128>>>(hA, S, hB, 64,  1835008);  // F  64->32

    root_kernel<<<4, 128>>>(hB, Wr, out);
}

// round 3
// speedup vs baseline: 4.6423x; 4.6423x over previous
#include <cuda_runtime.h>
#include <cstddef>

typedef unsigned long long u64;

// Scratch (static __device__ — no allocations allowed).
__device__ float g_S[1966080];    // softmaxed weights, all 4 layers
__device__ float g_hA[2097152];   // 512*256*16 (layer1 out, reused by layer3 out)
__device__ float g_hB[1048576];   // 512*128*16 (layer2 out, reused by layer4 out)

// ---------------- packed f32x2 helpers (dual-fp32 pipe, verified R2) -------
__device__ __forceinline__ void fma2(u64& d, u64 a, u64 b) {
    asm("fma.rn.f32x2 %0, %1, %2, %0;" : "+l"(d) : "l"(a), "l"(b));
}
__device__ __forceinline__ u64 mul2(u64 a, u64 b) {
    u64 d; asm("mul.rn.f32x2 %0, %1, %2;" : "=l"(d) : "l"(a), "l"(b)); return d;
}
__device__ __forceinline__ u64 pack2(float x) {
    u64 d; asm("mov.b64 %0, {%1, %1};" : "=l"(d) : "f"(x)); return d;
}
__device__ __forceinline__ void unpack2(u64 a, float& lo, float& hi) {
    asm("mov.b64 {%0, %1}, %2;" : "=f"(lo), "=f"(hi) : "l"(a));
}

// ---------------------------------------------------------------------------
// Kernel 1: weight softmax. One block per f-slice (480 blocks, 256 threads).
// ---------------------------------------------------------------------------
__global__ void __launch_bounds__(256) wsoftmax_kernel(
    const float* __restrict__ W1, const float* __restrict__ W2,
    const float* __restrict__ W3, const float* __restrict__ W4)
{
    __shared__ float Ssm[4096];
    __shared__ float red[256];
    __shared__ float mxk[16];

    const int bx = blockIdx.x;
    const int t  = threadIdx.x;
    const float* W; float* S; int f;
    if (bx < 256)      { W = W1; S = g_S;           f = bx;       }
    else if (bx < 384) { W = W2; S = g_S + 1048576; f = bx - 256; }
    else if (bx < 448) { W = W3; S = g_S + 1572864; f = bx - 384; }
    else               { W = W4; S = g_S + 1835008; f = bx - 448; }

    const float4* Wg = (const float4*)(W + (size_t)f * 4096);
    float4*       Sg = (float4*)(S + (size_t)f * 4096);

    #pragma unroll
    for (int q = 0; q < 4; q++) ((float4*)Ssm)[t + 256 * q] = Wg[t + 256 * q];
    __syncthreads();

    const int k = t & 15;
    const int g = t >> 4;

    float pm = -1e30f;
    #pragma unroll
    for (int mm = 0; mm < 16; mm++) pm = fmaxf(pm, Ssm[(g * 16 + mm) * 16 + k]);
    red[g * 16 + k] = pm;
    __syncthreads();
    #pragma unroll
    for (int st = 8; st > 0; st >>= 1) {
        if (g < st) red[g * 16 + k] = fmaxf(red[g * 16 + k], red[(g + st) * 16 + k]);
        __syncthreads();
    }
    if (g == 0) mxk[k] = red[k];
    __syncthreads();

    const float mx = mxk[k];
    float ps = 0.f;
    #pragma unroll
    for (int mm = 0; mm < 16; mm++) {
        int idx = (g * 16 + mm) * 16 + k;
        float e = __expf(Ssm[idx] - mx);
        Ssm[idx] = e;
        ps += e;
    }
    __syncthreads();
    red[g * 16 + k] = ps;
    __syncthreads();
    #pragma unroll
    for (int st = 8; st > 0; st >>= 1) {
        if (g < st) red[g * 16 + k] += red[(g + st) * 16 + k];
        __syncthreads();
    }
    const float inv = 1.f / red[k];
    #pragma unroll
    for (int mm = 0; mm < 16; mm++) Ssm[(g * 16 + mm) * 16 + k] *= inv;
    __syncthreads();

    #pragma unroll
    for (int q = 0; q < 4; q++) Sg[t + 256 * q] = ((float4*)Ssm)[t + 256 * q];
}

// ---------------------------------------------------------------------------
// Kernel 2: one SPN layer. Thread-per-n, BROADCAST smem reads (all lanes read
// the same S address — N=1 on the crossbar), f32x2 packed FMA mainloop.
//   block = (f_out, n-tile of NT=blockDim.x threads)
//   a packed in registers (i-loop unrolled), b in a pad-17 per-thread smem
//   row (stride 17 across lanes = bank permutation, conflict-free).
// Per (i,j): 4x broadcast LDS.128 + 1 mul2 + 8 fma2.
// ---------------------------------------------------------------------------
__global__ void layer_kernel(
    const float* __restrict__ hin, const float* __restrict__ Sall,
    float* __restrict__ hout, int F_in, int s_off)
{
    extern __shared__ float sm[];
    float* Ssm  = sm;                         // 4096 floats
    const int NT  = blockDim.x;
    const int tid = threadIdx.x;
    float* Brow = sm + 4096 + tid * 17;       // per-thread padded row

    const int f   = blockIdx.x;
    const int n   = blockIdx.y * NT + tid;
    const int F_out = F_in >> 1;

    // Cooperative stage of S_f (16KB), coalesced.
    {
        const float4* Sg = (const float4*)(Sall + (size_t)s_off + (size_t)f * 4096);
        for (int idx = tid; idx < 1024; idx += NT)
            ((float4*)Ssm)[idx] = Sg[idx];
    }

    // Load children: 16 left + 16 right floats.
    const float4* hp = (const float4*)(hin + ((size_t)n * F_in + 2 * f) * 16);
    float v[32];
    #pragma unroll
    for (int q = 0; q < 8; q++) ((float4*)v)[q] = hp[q];

    float lmax = v[0], rmax = v[16];
    #pragma unroll
    for (int i = 1; i < 16; i++) {
        lmax = fmaxf(lmax, v[i]);
        rmax = fmaxf(rmax, v[16 + i]);
    }

    u64 a2[16];
    #pragma unroll
    for (int i = 0; i < 16; i++) a2[i] = pack2(__expf(v[i] - lmax));
    #pragma unroll
    for (int j = 0; j < 16; j++) Brow[j] = __expf(v[16 + j] - rmax);

    __syncthreads();   // Ssm ready (Brow is per-thread private)

    u64 acc[8];
    #pragma unroll
    for (int q = 0; q < 8; q++) acc[q] = 0ull;

    for (int j = 0; j < 16; j++) {            // rolled: ~3.8KB body
        const u64 b2 = pack2(Brow[j]);
        const u64* Sj = (const u64*)(Ssm + j * 16);   // &S[i=0][j][k=0]
        #pragma unroll
        for (int i = 0; i < 16; i++) {
            const u64 p2 = mul2(a2[i], b2);
            const u64* q = Sj + i * 128;      // next i-row: +256 floats
            fma2(acc[0], p2, q[0]); fma2(acc[1], p2, q[1]);
            fma2(acc[2], p2, q[2]); fma2(acc[3], p2, q[3]);
            fma2(acc[4], p2, q[4]); fma2(acc[5], p2, q[5]);
            fma2(acc[6], p2, q[6]); fma2(acc[7], p2, q[7]);
        }
    }

    const float base = lmax + rmax;
    float o[16];
    #pragma unroll
    for (int q = 0; q < 8; q++) {
        float lo, hi; unpack2(acc[q], lo, hi);
        o[2 * q]     = __logf(lo) + base;
        o[2 * q + 1] = __logf(hi) + base;
    }
    float4* op = (float4*)(hout + ((size_t)n * F_out + f) * 16);
    #pragma unroll
    for (int q = 0; q < 4; q++) op[q] = ((float4*)o)[q];
}

// ---------------------------------------------------------------------------
// Kernel 3: root.
// ---------------------------------------------------------------------------
__global__ void root_kernel(const float* __restrict__ h4,
                            const float* __restrict__ Wroot,
                            float* __restrict__ out)
{
    int n = blockIdx.x * blockDim.x + threadIdx.x;
    if (n >= 512) return;

    float s[16];
    #pragma unroll
    for (int k = 0; k < 16; k++) s[k] = 0.f;

    const float4* hp = (const float4*)(h4 + (size_t)n * 512);
    #pragma unroll
    for (int t = 0; t < 128; t++) {
        float4 q = hp[t];
        const int k0 = (t & 3) * 4;
        s[k0 + 0] += q.x; s[k0 + 1] += q.y; s[k0 + 2] += q.z; s[k0 + 3] += q.w;
    }

    float w[16];
    #pragma unroll
    for (int k = 0; k < 16; k++) w[k] = Wroot[k];
    float wm = w[0];
    #pragma unroll
    for (int k = 1; k < 16; k++) wm = fmaxf(wm, w[k]);
    float Z = 0.f;
    #pragma unroll
    for (int k = 0; k < 16; k++) Z += __expf(w[k] - wm);
    const float lz = __logf(Z) + wm;

    float t[16];
    float tm = -1e30f;
    #pragma unroll
    for (int k = 0; k < 16; k++) {
        t[k] = s[k] + w[k] - lz;
        tm = fmaxf(tm, t[k]);
    }
    float ss = 0.f;
    #pragma unroll
    for (int k = 0; k < 16; k++) ss += __expf(t[k] - tm);
    out[n] = __logf(ss) + tm;
}

// ---------------------------------------------------------------------------
extern "C" void kernel_launch(void* const* d_in, const int* in_sizes, int n_in,
                              void* d_out, int out_size)
{
    const float* x  = (const float*)d_in[0];
    const float* W1 = (const float*)d_in[1];
    const float* W2 = (const float*)d_in[2];
    const float* W3 = (const float*)d_in[3];
    const float* W4 = (const float*)d_in[4];
    const float* Wr = (const float*)d_in[5];
    float* out = (float*)d_out;

    float *S, *hA, *hB;
    cudaGetSymbolAddress((void**)&S,  g_S);
    cudaGetSymbolAddress((void**)&hA, g_hA);
    cudaGetSymbolAddress((void**)&hB, g_hB);

    wsoftmax_kernel<<<480, 256>>>(W1, W2, W3, W4);

    // dynamic smem: 16KB (S) + NT*17*4 (b rows)
    const size_t smem128 = 4096 * 4 + 128 * 17 * 4;
    const size_t smem64  = 4096 * 4 +  64 * 17 * 4;
    const size_t smem32  = 4096 * 4 +  32 * 17 * 4;

    layer_kernel<<<dim3(256, 4),  128, smem128>>>(x,  S, hA, 512, 0);       // 1024 blocks
    layer_kernel<<<dim3(128, 4),  128, smem128>>>(hA, S, hB, 256, 1048576); //  512 blocks
    layer_kernel<<<dim3(64, 8),    64, smem64 >>>(hB, S, hA, 128, 1572864); //  512 blocks
    layer_kernel<<<dim3(32, 16),   32, smem32 >>>(hA, S, hB, 64,  1835008); //  512 blocks

    root_kernel<<<4, 128>>>(hB, Wr, out);
}

// round 4
// speedup vs baseline: 4.8965x; 1.0548x over previous
#include <cuda_runtime.h>
#include <cstddef>

typedef unsigned long long u64;

// Scratch (static __device__ — no allocations allowed).
__device__ float g_S[1966080];    // softmaxed weights, all 4 layers
__device__ float g_hA[2097152];   // 512*256*16 (layer1 out, reused by layer3 out)
__device__ float g_hB[1048576];   // 512*128*16 (layer2 out, reused by layer4 out)

// ---------------- packed f32x2 helpers (dual-fp32 pipe) --------------------
__device__ __forceinline__ void fma2(u64& d, u64 a, u64 b) {
    asm("fma.rn.f32x2 %0, %1, %2, %0;" : "+l"(d) : "l"(a), "l"(b));
}
__device__ __forceinline__ u64 mul2(u64 a, u64 b) {
    u64 d; asm("mul.rn.f32x2 %0, %1, %2;" : "=l"(d) : "l"(a), "l"(b)); return d;
}
__device__ __forceinline__ u64 pack2(float x) {
    u64 d; asm("mov.b64 %0, {%1, %1};" : "=l"(d) : "f"(x)); return d;
}
__device__ __forceinline__ void unpack2(u64 a, float& lo, float& hi) {
    asm("mov.b64 {%0, %1}, %2;" : "=f"(lo), "=f"(hi) : "l"(a));
}

// ---------------------------------------------------------------------------
// Kernel 1: weight softmax. One block per f-slice (480 blocks, 256 threads).
// ---------------------------------------------------------------------------
__global__ void __launch_bounds__(256) wsoftmax_kernel(
    const float* __restrict__ W1, const float* __restrict__ W2,
    const float* __restrict__ W3, const float* __restrict__ W4)
{
    __shared__ float Ssm[4096];
    __shared__ float red[256];
    __shared__ float mxk[16];

    const int bx = blockIdx.x;
    const int t  = threadIdx.x;
    const float* W; float* S; int f;
    if (bx < 256)      { W = W1; S = g_S;           f = bx;       }
    else if (bx < 384) { W = W2; S = g_S + 1048576; f = bx - 256; }
    else if (bx < 448) { W = W3; S = g_S + 1572864; f = bx - 384; }
    else               { W = W4; S = g_S + 1835008; f = bx - 448; }

    const float4* Wg = (const float4*)(W + (size_t)f * 4096);
    float4*       Sg = (float4*)(S + (size_t)f * 4096);

    #pragma unroll
    for (int q = 0; q < 4; q++) ((float4*)Ssm)[t + 256 * q] = Wg[t + 256 * q];
    __syncthreads();

    const int k = t & 15;
    const int g = t >> 4;

    float pm = -1e30f;
    #pragma unroll
    for (int mm = 0; mm < 16; mm++) pm = fmaxf(pm, Ssm[(g * 16 + mm) * 16 + k]);
    red[g * 16 + k] = pm;
    __syncthreads();
    #pragma unroll
    for (int st = 8; st > 0; st >>= 1) {
        if (g < st) red[g * 16 + k] = fmaxf(red[g * 16 + k], red[(g + st) * 16 + k]);
        __syncthreads();
    }
    if (g == 0) mxk[k] = red[k];
    __syncthreads();

    const float mx = mxk[k];
    float ps = 0.f;
    #pragma unroll
    for (int mm = 0; mm < 16; mm++) {
        int idx = (g * 16 + mm) * 16 + k;
        float e = __expf(Ssm[idx] - mx);
        Ssm[idx] = e;
        ps += e;
    }
    __syncthreads();
    red[g * 16 + k] = ps;
    __syncthreads();
    #pragma unroll
    for (int st = 8; st > 0; st >>= 1) {
        if (g < st) red[g * 16 + k] += red[(g + st) * 16 + k];
        __syncthreads();
    }
    const float inv = 1.f / red[k];
    #pragma unroll
    for (int mm = 0; mm < 16; mm++) Ssm[(g * 16 + mm) * 16 + k] *= inv;
    __syncthreads();

    #pragma unroll
    for (int q = 0; q < 4; q++) Sg[t + 256 * q] = ((float4*)Ssm)[t + 256 * q];
}

// ---------------------------------------------------------------------------
// Kernel 2: one SPN layer, k-split by KS (template).
//   Block = 128 threads = NPB n-slots x KS k-threads. Thread (nl, s) owns
//   k in [KO*s, KO*s+KO), KO = 16/KS.
//   S reads: n-groups broadcast (same addr), s-groups offset by KO*4B ->
//   distinct banks. Conflict-free. No cross-thread reduce; coalesced stores.
//   Inputs staged in pad-36 smem rows (one global load per n, not per thread);
//   b staged in pad-20 smem rows by s==0.
// ---------------------------------------------------------------------------
template<int KS>
__global__ void __launch_bounds__(128) layer_kernel(
    const float* __restrict__ hin, const float* __restrict__ Sall,
    float* __restrict__ hout, int F_in, int s_off)
{
    constexpr int NPB = 128 / KS;
    constexpr int KO  = 16 / KS;
    extern __shared__ float sm[];
    float* Ssm = sm;                              // 4096 floats

    const int tid = threadIdx.x;
    const int f   = blockIdx.x;
    const int F_out = F_in >> 1;

    // Stage S_f (16KB), coalesced.
    {
        const float4* Sg = (const float4*)(Sall + (size_t)s_off + (size_t)f * 4096);
        #pragma unroll
        for (int q = 0; q < 8; q++) ((float4*)Ssm)[tid + 128 * q] = Sg[tid + 128 * q];
    }

    if constexpr (KS == 1) {
        // --- R3 path: thread-per-n, b in private pad-17 row ---
        float* Brow = sm + 4096 + tid * 17;
        const int n = blockIdx.y * 128 + tid;

        const float4* hp = (const float4*)(hin + ((size_t)n * F_in + 2 * f) * 16);
        float v[32];
        #pragma unroll
        for (int q = 0; q < 8; q++) ((float4*)v)[q] = hp[q];

        float lmax = v[0], rmax = v[16];
        #pragma unroll
        for (int i = 1; i < 16; i++) {
            lmax = fmaxf(lmax, v[i]);
            rmax = fmaxf(rmax, v[16 + i]);
        }
        u64 a2[16];
        #pragma unroll
        for (int i = 0; i < 16; i++) a2[i] = pack2(__expf(v[i] - lmax));
        #pragma unroll
        for (int j = 0; j < 16; j++) Brow[j] = __expf(v[16 + j] - rmax);

        __syncthreads();

        u64 acc[8];
        #pragma unroll
        for (int q = 0; q < 8; q++) acc[q] = 0ull;

        for (int j = 0; j < 16; j++) {
            const u64 b2 = pack2(Brow[j]);
            const u64* Sj = (const u64*)(Ssm + j * 16);
            #pragma unroll
            for (int i = 0; i < 16; i++) {
                const u64 p2 = mul2(a2[i], b2);
                const u64* q = Sj + i * 128;
                fma2(acc[0], p2, q[0]); fma2(acc[1], p2, q[1]);
                fma2(acc[2], p2, q[2]); fma2(acc[3], p2, q[3]);
                fma2(acc[4], p2, q[4]); fma2(acc[5], p2, q[5]);
                fma2(acc[6], p2, q[6]); fma2(acc[7], p2, q[7]);
            }
        }

        const float base = lmax + rmax;
        float o[16];
        #pragma unroll
        for (int q = 0; q < 8; q++) {
            float lo, hi; unpack2(acc[q], lo, hi);
            o[2 * q]     = __logf(lo) + base;
            o[2 * q + 1] = __logf(hi) + base;
        }
        float4* op = (float4*)(hout + ((size_t)n * F_out + f) * 16);
        #pragma unroll
        for (int q = 0; q < 4; q++) op[q] = ((float4*)o)[q];
    } else {
        // --- k-split path ---
        float* Hsm = sm + 4096;            // NPB * 36
        float* Bsm = Hsm + NPB * 36;       // NPB * 20
        const int s  = tid % KS;
        const int nl = tid / KS;
        const int n0 = blockIdx.y * NPB;

        // Stage inputs: one global read per n (coalesced 128B per n-row).
        #pragma unroll
        for (int idx = tid; idx < NPB * 8; idx += 128) {
            const int n_l = idx >> 3, q = idx & 7;
            float4 val = ((const float4*)(hin +
                ((size_t)(n0 + n_l) * F_in + 2 * f) * 16))[q];
            ((float4*)(Hsm + n_l * 36))[q] = val;
        }
        __syncthreads();

        float v[32];
        #pragma unroll
        for (int q = 0; q < 8; q++) ((float4*)v)[q] = ((float4*)(Hsm + nl * 36))[q];

        float lmax = v[0], rmax = v[16];
        #pragma unroll
        for (int i = 1; i < 16; i++) {
            lmax = fmaxf(lmax, v[i]);
            rmax = fmaxf(rmax, v[16 + i]);
        }
        u64 a2[16];
        #pragma unroll
        for (int i = 0; i < 16; i++) a2[i] = pack2(__expf(v[i] - lmax));
        if (s == 0) {
            #pragma unroll
            for (int j = 0; j < 16; j++) Bsm[nl * 20 + j] = __expf(v[16 + j] - rmax);
        }
        __syncthreads();

        u64 acc[KO / 2];
        #pragma unroll
        for (int u = 0; u < KO / 2; u++) acc[u] = 0ull;

        const float* Bme = Bsm + nl * 20;
        #pragma unroll 2
        for (int j = 0; j < 16; j++) {
            const u64 b2 = pack2(Bme[j]);
            const float* Sbase = Ssm + j * 16 + KO * s;
            #pragma unroll
            for (int i = 0; i < 16; i++) {
                const u64 p2 = mul2(a2[i], b2);
                const u64* q = (const u64*)(Sbase + i * 256);
                #pragma unroll
                for (int u = 0; u < KO / 2; u++) fma2(acc[u], p2, q[u]);
            }
        }

        const float base = lmax + rmax;
        float o[KO];
        #pragma unroll
        for (int u = 0; u < KO / 2; u++) {
            float lo, hi; unpack2(acc[u], lo, hi);
            o[2 * u]     = __logf(lo) + base;
            o[2 * u + 1] = __logf(hi) + base;
        }
        float* op = hout + ((size_t)(n0 + nl) * F_out + f) * 16 + KO * s;
        if constexpr (KO >= 4) {
            #pragma unroll
            for (int q = 0; q < KO / 4; q++) ((float4*)op)[q] = ((float4*)o)[q];
        } else {
            ((float2*)op)[0] = make_float2(o[0], o[1]);
        }
    }
}

// ---------------------------------------------------------------------------
// Kernel 3: root. Block per n (512 blocks, 32 threads), warp-shfl reduce.
// ---------------------------------------------------------------------------
__global__ void __launch_bounds__(32) root_kernel(
    const float* __restrict__ h4, const float* __restrict__ Wroot,
    float* __restrict__ out)
{
    const int n = blockIdx.x;
    const int t = threadIdx.x;
    const float4* hp = (const float4*)(h4 + (size_t)n * 512);

    float4 a = make_float4(0.f, 0.f, 0.f, 0.f);
    #pragma unroll
    for (int r = 0; r < 4; r++) {
        float4 q = hp[t + 32 * r];
        a.x += q.x; a.y += q.y; a.z += q.z; a.w += q.w;
    }
    // lane t holds partial for k-quad (t&3); reduce lanes with equal t&3
    #pragma unroll
    for (int st = 4; st <= 16; st <<= 1) {
        a.x += __shfl_xor_sync(0xffffffffu, a.x, st);
        a.y += __shfl_xor_sync(0xffffffffu, a.y, st);
        a.z += __shfl_xor_sync(0xffffffffu, a.z, st);
        a.w += __shfl_xor_sync(0xffffffffu, a.w, st);
    }
    __shared__ float sred[16];
    if (t < 4) { sred[4*t] = a.x; sred[4*t+1] = a.y; sred[4*t+2] = a.z; sred[4*t+3] = a.w; }
    __syncwarp();

    if (t == 0) {
        float w[16];
        #pragma unroll
        for (int k = 0; k < 16; k++) w[k] = Wroot[k];
        float wm = w[0];
        #pragma unroll
        for (int k = 1; k < 16; k++) wm = fmaxf(wm, w[k]);
        float Z = 0.f;
        #pragma unroll
        for (int k = 0; k < 16; k++) Z += __expf(w[k] - wm);
        const float lz = __logf(Z) + wm;

        float tv[16];
        float tm = -1e30f;
        #pragma unroll
        for (int k = 0; k < 16; k++) {
            tv[k] = sred[k] + w[k] - lz;
            tm = fmaxf(tm, tv[k]);
        }
        float ss = 0.f;
        #pragma unroll
        for (int k = 0; k < 16; k++) ss += __expf(tv[k] - tm);
        out[n] = __logf(ss) + tm;
    }
}

// ---------------------------------------------------------------------------
extern "C" void kernel_launch(void* const* d_in, const int* in_sizes, int n_in,
                              void* d_out, int out_size)
{
    const float* x  = (const float*)d_in[0];
    const float* W1 = (const float*)d_in[1];
    const float* W2 = (const float*)d_in[2];
    const float* W3 = (const float*)d_in[3];
    const float* W4 = (const float*)d_in[4];
    const float* Wr = (const float*)d_in[5];
    float* out = (float*)d_out;

    float *S, *hA, *hB;
    cudaGetSymbolAddress((void**)&S,  g_S);
    cudaGetSymbolAddress((void**)&hA, g_hA);
    cudaGetSymbolAddress((void**)&hB, g_hB);

    wsoftmax_kernel<<<480, 256>>>(W1, W2, W3, W4);

    // smem: KS=1: 16K + 128*17*4; KS>1: 16K + NPB*36*4 + NPB*20*4
    const size_t sm1 = 4096 * 4 + 128 * 17 * 4;            // 25088
    const size_t sm2 = 4096 * 4 + 64 * 36 * 4 + 64 * 20 * 4;  // 30720
    const size_t sm4 = 4096 * 4 + 32 * 36 * 4 + 32 * 20 * 4;  // 23552
    const size_t sm8 = 4096 * 4 + 16 * 36 * 4 + 16 * 20 * 4;  // 19968

    layer_kernel<1><<<dim3(256, 4),  128, sm1>>>(x,  S, hA, 512, 0);
    layer_kernel<2><<<dim3(128, 8),  128, sm2>>>(hA, S, hB, 256, 1048576);
    layer_kernel<4><<<dim3(64, 16),  128, sm4>>>(hB, S, hA, 128, 1572864);
    layer_kernel<8><<<dim3(32, 32),  128, sm8>>>(hA, S, hB, 64,  1835008);

    root_kernel<<<512, 32>>>(hB, Wr, out);
}

// round 5
// speedup vs baseline: 5.7196x; 1.1681x over previous
#include <cuda_runtime.h>
#include <cstddef>

typedef unsigned long long u64;

// Scratch (static __device__ — no allocations allowed).
__device__ float g_S[1966080];    // softmaxed weights, all 4 layers
__device__ float g_hA[2097152];   // 512*256*16 (layer1 out, reused by layer3 out)
__device__ float g_hB[1048576];   // 512*128*16 (layer2 out, reused by layer4 out)

// ---------------- packed f32x2 helpers (dual-fp32 pipe) --------------------
__device__ __forceinline__ void fma2(u64& d, u64 a, u64 b) {
    asm("fma.rn.f32x2 %0, %1, %2, %0;" : "+l"(d) : "l"(a), "l"(b));
}
__device__ __forceinline__ u64 pack2(float x) {
    u64 d; asm("mov.b64 %0, {%1, %1};" : "=l"(d) : "f"(x)); return d;
}
__device__ __forceinline__ void unpack2(u64 a, float& lo, float& hi) {
    asm("mov.b64 {%0, %1}, %2;" : "=f"(lo), "=f"(hi) : "l"(a));
}

// ---------------------------------------------------------------------------
// Kernel 1: weight softmax. One block per f-slice (480 blocks, 256 threads).
// ---------------------------------------------------------------------------
__global__ void __launch_bounds__(256) wsoftmax_kernel(
    const float* __restrict__ W1, const float* __restrict__ W2,
    const float* __restrict__ W3, const float* __restrict__ W4)
{
    __shared__ float Ssm[4096];
    __shared__ float red[256];
    __shared__ float mxk[16];

    const int bx = blockIdx.x;
    const int t  = threadIdx.x;
    const float* W; float* S; int f;
    if (bx < 256)      { W = W1; S = g_S;           f = bx;       }
    else if (bx < 384) { W = W2; S = g_S + 1048576; f = bx - 256; }
    else if (bx < 448) { W = W3; S = g_S + 1572864; f = bx - 384; }
    else               { W = W4; S = g_S + 1835008; f = bx - 448; }

    const float4* Wg = (const float4*)(W + (size_t)f * 4096);
    float4*       Sg = (float4*)(S + (size_t)f * 4096);

    #pragma unroll
    for (int q = 0; q < 4; q++) ((float4*)Ssm)[t + 256 * q] = Wg[t + 256 * q];
    __syncthreads();

    const int k = t & 15;
    const int g = t >> 4;

    float pm = -1e30f;
    #pragma unroll
    for (int mm = 0; mm < 16; mm++) pm = fmaxf(pm, Ssm[(g * 16 + mm) * 16 + k]);
    red[g * 16 + k] = pm;
    __syncthreads();
    #pragma unroll
    for (int st = 8; st > 0; st >>= 1) {
        if (g < st) red[g * 16 + k] = fmaxf(red[g * 16 + k], red[(g + st) * 16 + k]);
        __syncthreads();
    }
    if (g == 0) mxk[k] = red[k];
    __syncthreads();

    const float mx = mxk[k];
    float ps = 0.f;
    #pragma unroll
    for (int mm = 0; mm < 16; mm++) {
        int idx = (g * 16 + mm) * 16 + k;
        float e = __expf(Ssm[idx] - mx);
        Ssm[idx] = e;
        ps += e;
    }
    __syncthreads();
    red[g * 16 + k] = ps;
    __syncthreads();
    #pragma unroll
    for (int st = 8; st > 0; st >>= 1) {
        if (g < st) red[g * 16 + k] += red[(g + st) * 16 + k];
        __syncthreads();
    }
    const float inv = 1.f / red[k];
    #pragma unroll
    for (int mm = 0; mm < 16; mm++) Ssm[(g * 16 + mm) * 16 + k] *= inv;
    __syncthreads();

    #pragma unroll
    for (int q = 0; q < 4; q++) Sg[t + 256 * q] = ((float4*)Ssm)[t + 256 * q];
}

// ---------------------------------------------------------------------------
// Kernel 2: one SPN layer. NT=2 n-register-tiling x KS k-split (template).
//   128 threads = NSL n-slots x KS k-lanes; thread (nl,s) owns samples
//   n0 = base+nl, n1 = n0+NSL and k-chunk [KO*s, KO*s+KO), KO = 16/KS.
//   S reads: ONE wide load per (i,j) (KO/4 LDS.128 or 1 LDS.64); s-lanes hit
//   distinct consecutive banks, nl-lanes broadcast -> 1 wavefront/instr.
//   a0/a1 in registers (i unrolled), b in pad-17 per-n smem rows (j rolled).
//   acc in packed f32x2. No cross-thread reduce; coalesced stores.
// ---------------------------------------------------------------------------
template<int KS>
__global__ void __launch_bounds__(128) layer_kernel(
    const float* __restrict__ hin, const float* __restrict__ Sall,
    float* __restrict__ hout, int F_in, int s_off)
{
    constexpr int KO  = 16 / KS;     // k per thread
    constexpr int NSL = 128 / KS;    // n-slots per block (x2 via NT)
    extern __shared__ float sm[];
    float* Ssm   = sm;               // 4096 floats
    float* Brows = sm + 4096;        // 2*NSL rows of 17

    const int tid = threadIdx.x;
    const int s   = tid % KS;
    const int nl  = tid / KS;
    const int f   = blockIdx.x;
    const int F_out = F_in >> 1;
    const int n0 = blockIdx.y * (2 * NSL) + nl;
    const int n1 = n0 + NSL;

    // Stage S_f (16KB), coalesced.
    {
        const float4* Sg = (const float4*)(Sall + (size_t)s_off + (size_t)f * 4096);
        #pragma unroll
        for (int q = 0; q < 8; q++) ((float4*)Ssm)[tid + 128 * q] = Sg[tid + 128 * q];
    }

    // Load children for both samples (32 floats each).
    float v0[32], v1[32];
    {
        const float4* hp0 = (const float4*)(hin + ((size_t)n0 * F_in + 2 * f) * 16);
        const float4* hp1 = (const float4*)(hin + ((size_t)n1 * F_in + 2 * f) * 16);
        #pragma unroll
        for (int q = 0; q < 8; q++) {
            ((float4*)v0)[q] = hp0[q];
            ((float4*)v1)[q] = hp1[q];
        }
    }

    float l0 = v0[0], r0 = v0[16], l1 = v1[0], r1 = v1[16];
    #pragma unroll
    for (int i = 1; i < 16; i++) {
        l0 = fmaxf(l0, v0[i]);      r0 = fmaxf(r0, v0[16 + i]);
        l1 = fmaxf(l1, v1[i]);      r1 = fmaxf(r1, v1[16 + i]);
    }

    float a0[16], a1[16];
    #pragma unroll
    for (int i = 0; i < 16; i++) {
        a0[i] = __expf(v0[i] - l0);
        a1[i] = __expf(v1[i] - l1);
    }
    float* row0 = Brows + nl * 17;
    float* row1 = Brows + (NSL + nl) * 17;
    if (s == 0) {
        #pragma unroll
        for (int j = 0; j < 16; j++) {
            row0[j] = __expf(v0[16 + j] - r0);
            row1[j] = __expf(v1[16 + j] - r1);
        }
    }
    __syncthreads();

    u64 acc0[KO / 2], acc1[KO / 2];
    #pragma unroll
    for (int u = 0; u < KO / 2; u++) { acc0[u] = 0ull; acc1[u] = 0ull; }

    #pragma unroll 1
    for (int j = 0; j < 16; j++) {
        const float b0 = row0[j];
        const float b1 = row1[j];
        const float* Sj = Ssm + j * 16 + KO * s;
        #pragma unroll
        for (int i = 0; i < 16; i++) {
            const u64* q = (const u64*)(Sj + i * 256);
            const u64 p0 = pack2(a0[i] * b0);
            const u64 p1 = pack2(a1[i] * b1);
            #pragma unroll
            for (int u = 0; u < KO / 2; u++) {
                fma2(acc0[u], p0, q[u]);
                fma2(acc1[u], p1, q[u]);
            }
        }
    }

    // Epilogue: log + store (KO floats per sample, lanes s contiguous in k).
    const float base0 = l0 + r0;
    const float base1 = l1 + r1;
    float o0[KO], o1[KO];
    #pragma unroll
    for (int u = 0; u < KO / 2; u++) {
        float lo, hi;
        unpack2(acc0[u], lo, hi);
        o0[2 * u] = __logf(lo) + base0;  o0[2 * u + 1] = __logf(hi) + base0;
        unpack2(acc1[u], lo, hi);
        o1[2 * u] = __logf(lo) + base1;  o1[2 * u + 1] = __logf(hi) + base1;
    }
    float* op0 = hout + ((size_t)n0 * F_out + f) * 16 + KO * s;
    float* op1 = hout + ((size_t)n1 * F_out + f) * 16 + KO * s;
    if constexpr (KO >= 4) {
        #pragma unroll
        for (int q = 0; q < KO / 4; q++) {
            ((float4*)op0)[q] = ((float4*)o0)[q];
            ((float4*)op1)[q] = ((float4*)o1)[q];
        }
    } else {
        ((float2*)op0)[0] = make_float2(o0[0], o0[1]);
        ((float2*)op1)[0] = make_float2(o1[0], o1[1]);
    }
}

// ---------------------------------------------------------------------------
// Kernel 3: root. Block per n (512 blocks, 32 threads), warp-shfl reduce.
// ---------------------------------------------------------------------------
__global__ void __launch_bounds__(32) root_kernel(
    const float* __restrict__ h4, const float* __restrict__ Wroot,
    float* __restrict__ out)
{
    const int n = blockIdx.x;
    const int t = threadIdx.x;
    const float4* hp = (const float4*)(h4 + (size_t)n * 512);

    float4 a = make_float4(0.f, 0.f, 0.f, 0.f);
    #pragma unroll
    for (int r = 0; r < 4; r++) {
        float4 q = hp[t + 32 * r];
        a.x += q.x; a.y += q.y; a.z += q.z; a.w += q.w;
    }
    #pragma unroll
    for (int st = 4; st <= 16; st <<= 1) {
        a.x += __shfl_xor_sync(0xffffffffu, a.x, st);
        a.y += __shfl_xor_sync(0xffffffffu, a.y, st);
        a.z += __shfl_xor_sync(0xffffffffu, a.z, st);
        a.w += __shfl_xor_sync(0xffffffffu, a.w, st);
    }
    __shared__ float sred[16];
    if (t < 4) { sred[4*t] = a.x; sred[4*t+1] = a.y; sred[4*t+2] = a.z; sred[4*t+3] = a.w; }
    __syncwarp();

    if (t == 0) {
        float w[16];
        #pragma unroll
        for (int k = 0; k < 16; k++) w[k] = Wroot[k];
        float wm = w[0];
        #pragma unroll
        for (int k = 1; k < 16; k++) wm = fmaxf(wm, w[k]);
        float Z = 0.f;
        #pragma unroll
        for (int k = 0; k < 16; k++) Z += __expf(w[k] - wm);
        const float lz = __logf(Z) + wm;

        float tv[16];
        float tm = -1e30f;
        #pragma unroll
        for (int k = 0; k < 16; k++) {
            tv[k] = sred[k] + w[k] - lz;
            tm = fmaxf(tm, tv[k]);
        }
        float ss = 0.f;
        #pragma unroll
        for (int k = 0; k < 16; k++) ss += __expf(tv[k] - tm);
        out[n] = __logf(ss) + tm;
    }
}

// ---------------------------------------------------------------------------
extern "C" void kernel_launch(void* const* d_in, const int* in_sizes, int n_in,
                              void* d_out, int out_size)
{
    const float* x  = (const float*)d_in[0];
    const float* W1 = (const float*)d_in[1];
    const float* W2 = (const float*)d_in[2];
    const float* W3 = (const float*)d_in[3];
    const float* W4 = (const float*)d_in[4];
    const float* Wr = (const float*)d_in[5];
    float* out = (float*)d_out;

    float *S, *hA, *hB;
    cudaGetSymbolAddress((void**)&S,  g_S);
    cudaGetSymbolAddress((void**)&hA, g_hA);
    cudaGetSymbolAddress((void**)&hB, g_hB);

    wsoftmax_kernel<<<480, 256>>>(W1, W2, W3, W4);

    // smem = 16KB (S) + 2*NSL*17*4 (b rows)
    const size_t sm1 = 16384 + 2 * 128 * 17 * 4;  // 33792
    const size_t sm2 = 16384 + 2 *  64 * 17 * 4;  // 25088
    const size_t sm4 = 16384 + 2 *  32 * 17 * 4;  // 20736
    const size_t sm8 = 16384 + 2 *  16 * 17 * 4;  // 18560

    // All layers: 512 blocks, 2048 warps -> ~13.8 warps/SM, FMA-bound.
    layer_kernel<1><<<dim3(256, 2),  128, sm1>>>(x,  S, hA, 512, 0);
    layer_kernel<2><<<dim3(128, 4),  128, sm2>>>(hA, S, hB, 256, 1048576);
    layer_kernel<4><<<dim3(64, 8),   128, sm4>>>(hB, S, hA, 128, 1572864);
    layer_kernel<8><<<dim3(32, 16),  128, sm8>>>(hA, S, hB, 64,  1835008);

    root_kernel<<<512, 32>>>(hB, Wr, out);
}